// round 13
// baseline (speedup 1.0000x reference)
#include <cuda_runtime.h>
#include <cuda_fp16.h>
#include <cstdint>

#define BATCH 4
#define CH    64
#define HH    512
#define WWID  512
#define OH    256
#define OW    256
#define REDC  16
#define NWGT  36

#define NCTA     148
#define NROWU    4096           // 8 columns (4b x 2 strips) * 512 rows
#define STRIP    256
#define SLOT_PX  258
#define SLOT_B   37152          // 258 px * 144 B
#define NWU4     4608           // conv weight uint4 entries: 18*8*32

// conv smem byte offsets
#define OFF_W 0                 // uint4[4608] = 73728 B
#define OFF_X 73728             // 4 ring slots * 37152 = 148608 B
#define OFF_B 222336            // bias 64 floats
#define CONV_SMEM_BYTES 222592

// Scratch
__device__ __align__(16) __half g_yh[(size_t)BATCH * HH * WWID * CH];   // y fp16 NHWC
__device__ __align__(16) uint4  g_wh[NWU4];                             // conv weight frags
__device__ __align__(16) uint2  g_w3f[1024];                            // w3 frags

// ---------------- helpers ----------------
#define CP16(dst, src, sz) \
    asm volatile("cp.async.cg.shared.global [%0], [%1], 16, %2;" \
        :: "r"(dst), "l"(src), "r"(sz) : "memory")
#define CP_COMMIT() asm volatile("cp.async.commit_group;" ::: "memory")
#define CP_WAIT0()  asm volatile("cp.async.wait_group 0;" ::: "memory")

__device__ __forceinline__ void mma_f16(float* d, const uint32_t* a,
                                        uint32_t b0, uint32_t b1) {
    asm volatile(
        "mma.sync.aligned.m16n8k16.row.col.f32.f16.f16.f32 "
        "{%0,%1,%2,%3},{%4,%5,%6,%7},{%8,%9},{%0,%1,%2,%3};"
        : "+f"(d[0]), "+f"(d[1]), "+f"(d[2]), "+f"(d[3])
        : "r"(a[0]), "r"(a[1]), "r"(a[2]), "r"(a[3]), "r"(b0), "r"(b1));
}
#define LDMX4(r, addr) \
    asm volatile("ldmatrix.sync.aligned.m8n8.x4.shared.b16 {%0,%1,%2,%3}, [%4];" \
        : "=r"((r)[0]), "=r"((r)[1]), "=r"((r)[2]), "=r"((r)[3]) : "r"(addr))

// ---------------------------------------------------------------------------
// Pack conv weights: uint4 entry idx = ch*256 + nt*32 + lane holds both kk
// halves. Also w3 frags.
// ---------------------------------------------------------------------------
__global__ __launch_bounds__(256) void wpack_kernel(const float* __restrict__ w1,
                                                    const float* __restrict__ w3)
{
    int idx = blockIdx.x * 256 + threadIdx.x;
    if (idx < NWU4) {
        int lane = idx & 31;
        int nt   = (idx >> 5) & 7;
        int ch   = idx >> 8;
        int tap = ch >> 1, sec = ch & 1;
        int oc = nt * 8 + (lane >> 2);
        uint4 v;
#pragma unroll
        for (int kk = 0; kk < 2; kk++) {
            int ic0 = sec * 32 + kk * 16 + 2 * (lane & 3);
            __half2 h0 = __floats2half2_rn(w1[(oc * 64 + ic0) * 9 + tap],
                                           w1[(oc * 64 + ic0 + 1) * 9 + tap]);
            __half2 h1 = __floats2half2_rn(w1[(oc * 64 + ic0 + 8) * 9 + tap],
                                           w1[(oc * 64 + ic0 + 9) * 9 + tap]);
            if (kk == 0) { v.x = *(uint32_t*)&h0; v.y = *(uint32_t*)&h1; }
            else         { v.z = *(uint32_t*)&h0; v.w = *(uint32_t*)&h1; }
        }
        g_wh[idx] = v;
    }
    if (idx < 1024) {
        int lane = idx & 31;
        int nt   = (idx >> 5) & 7;
        int kk   = idx >> 8;
        int oc = nt * 8 + (lane >> 2);
        int c0 = kk * 16 + 2 * (lane & 3);
        __half2 h0 = __floats2half2_rn(w3[oc * 64 + c0],     w3[oc * 64 + c0 + 1]);
        __half2 h1 = __floats2half2_rn(w3[oc * 64 + c0 + 8], w3[oc * 64 + c0 + 9]);
        uint2 v;
        v.x = *(uint32_t*)&h0;
        v.y = *(uint32_t*)&h1;
        g_w3f[idx] = v;
    }
}

// ---------------------------------------------------------------------------
// Persistent fp16 mma conv3x3 + bias + relu -> g_yh (fp16 NHWC).
// 148 CTAs x 512 thr; warps 0-7 compute (m32 x n64), warps 8-15 produce by
// reading x DIRECTLY in NCHW fp32, converting to fp16, scattering to smem.
// Producer unit u in [0,136): tb = u%17, cb = u/17; t = tb*4+(lane&3) (<66),
// ch = cb*8+(lane>>2). Covers all 258 px x 64 ch exactly once.
// ---------------------------------------------------------------------------
__global__ __launch_bounds__(512, 1) void conv_mma_kernel(
    const float* __restrict__ x, const float* __restrict__ b1)
{
    extern __shared__ char smem[];
    uint4* s_w  = (uint4*)(smem + OFF_W);
    float* s_bias = (float*)(smem + OFF_B);

    int tid = threadIdx.x;
    int warpid = tid >> 5;
    int lane = tid & 31;
    int qr = lane >> 2, qc = lane & 3;
    int cta = blockIdx.x;

    uint32_t sb  = (uint32_t)__cvta_generic_to_shared(smem);
    uint32_t sxb = sb + OFF_X;

    for (int i = tid; i < NWU4; i += 512)
        CP16(sb + OFF_W + i * 16, (const char*)g_wh + i * 16, 16);
    if (tid < 64) s_bias[tid] = b1[tid];
    CP_COMMIT();
    CP_WAIT0();
    __syncthreads();

    int pw = warpid - 8;     // producer warp index 0..7
    int s_idx = (int)((long long)cta * NROWU / NCTA);
    int e_idx = (int)((long long)(cta + 1) * NROWU / NCTA);

    int ms = (warpid & 7) * 32;
    uint32_t laneoff = (uint32_t)((lane & 15) * 144 + ((lane >> 4) & 1) * 16);

    int wbase = 0;
    int b = 0;

    auto load_row = [&](int ar, int sl) {
        bool rok = ((unsigned)ar < 512u);
        const float* xr = x + ((size_t)(b * 64) << 18) + ((size_t)(rok ? ar : 0) << 9);
        int c = lane >> 2, q = lane & 3;
        char* dst = smem + OFF_X + sl * SLOT_B;
#pragma unroll 1
        for (int u = pw; u < 136; u += 8) {
            int tb = u % 17;
            int cb = u / 17;
            int t  = tb * 4 + q;            // 0..67, valid < 66
            int ch = cb * 8 + c;            // 0..63
            int gwa = wbase - 4 + 4 * t;    // aligned gmem col base
            bool lok = rok && (t < 66) && (gwa >= 0) && (gwa <= 508);
            float4 v = make_float4(0.f, 0.f, 0.f, 0.f);
            if (lok) v = *(const float4*)(xr + ((size_t)ch << 18) + gwa);
            if (t < 66) {
                int px0 = 4 * t - 3;
                __half h0 = __float2half(v.x), h1 = __float2half(v.y);
                __half h2 = __float2half(v.z), h3 = __float2half(v.w);
                if ((unsigned)(px0 + 0) < 258u) *(__half*)(dst + (px0 + 0) * 144 + ch * 2) = h0;
                if ((unsigned)(px0 + 1) < 258u) *(__half*)(dst + (px0 + 1) * 144 + ch * 2) = h1;
                if ((unsigned)(px0 + 2) < 258u) *(__half*)(dst + (px0 + 2) * 144 + ch * 2) = h2;
                if ((unsigned)(px0 + 3) < 258u) *(__half*)(dst + (px0 + 3) * 144 + ch * 2) = h3;
            }
        }
    };

    int curcol = -1;
    for (int idx = s_idx; idx < e_idx; idx++) {
        int col = idx >> 9;
        int h = idx & 511;
        b = col >> 1;
        int strip = col & 1;
        wbase = strip * STRIP;

        if (warpid >= 8 && col != curcol) {
            load_row(h - 1, (h - 1) & 3);
            load_row(h,     h & 3);
            load_row(h + 1, (h + 1) & 3);
        }
        curcol = col;
        __syncthreads();   // [A] rows h-1..h+1 visible

        if (warpid < 8) {
            float acc[2][8][4];
#pragma unroll
            for (int f = 0; f < 2; f++)
#pragma unroll
                for (int nt = 0; nt < 8; nt++)
#pragma unroll
                    for (int j = 0; j < 4; j++) acc[f][nt][j] = 0.f;

#pragma unroll 1
            for (int ch = 0; ch < 18; ch++) {
                int tap = ch >> 1, sec = ch & 1;
                int kh = tap / 3, kw = tap - kh * 3;
                uint32_t abase = sxb + ((h + kh - 1) & 3) * SLOT_B
                               + (ms + kw) * 144 + sec * 64 + laneoff;
                uint32_t a0[2][4], a1[2][4];
                LDMX4(a0[0], abase);
                LDMX4(a0[1], abase + 16 * 144);
                LDMX4(a1[0], abase + 32);
                LDMX4(a1[1], abase + 32 + 16 * 144);
                const uint4* wq = s_w + ch * 256 + lane;
                uint4 bv[8];
#pragma unroll
                for (int nt = 0; nt < 8; nt++) bv[nt] = wq[nt * 32];
#pragma unroll
                for (int nt = 0; nt < 8; nt++) {
                    mma_f16(acc[0][nt], a0[0], bv[nt].x, bv[nt].y);
                    mma_f16(acc[1][nt], a0[1], bv[nt].x, bv[nt].y);
                }
#pragma unroll
                for (int nt = 0; nt < 8; nt++) {
                    mma_f16(acc[0][nt], a1[0], bv[nt].z, bv[nt].w);
                    mma_f16(acc[1][nt], a1[1], bv[nt].z, bv[nt].w);
                }
            }
            size_t rowoff = ((size_t)(b * 512 + h) << 9);
#pragma unroll
            for (int f = 0; f < 2; f++) {
                int px0 = wbase + ms + f * 16 + qr;
#pragma unroll
                for (int nt = 0; nt < 8; nt++) {
                    int oc0 = nt * 8 + qc * 2;
                    float bs0 = s_bias[oc0], bs1 = s_bias[oc0 + 1];
                    __half2 lo = __floats2half2_rn(fmaxf(acc[f][nt][0] + bs0, 0.f),
                                                   fmaxf(acc[f][nt][1] + bs1, 0.f));
                    __half2 hi = __floats2half2_rn(fmaxf(acc[f][nt][2] + bs0, 0.f),
                                                   fmaxf(acc[f][nt][3] + bs1, 0.f));
                    *(__half2*)(g_yh + ((rowoff + px0) << 6) + oc0) = lo;
                    *(__half2*)(g_yh + ((rowoff + px0 + 8) << 6) + oc0) = hi;
                }
            }
        } else {
            load_row(h + 2, (h + 2) & 3);
        }
        __syncthreads();   // [B]
    }
}

// ---------------------------------------------------------------------------
// Fused tail: 256 threads (8 warps), warp = 32 consecutive output pixels.
// ---------------------------------------------------------------------------
__global__ __launch_bounds__(256, 3) void fuse_kernel(
    const float* __restrict__ wr, const float* __restrict__ br,
    const float* __restrict__ gamma, const float* __restrict__ beta,
    const float* __restrict__ mean,  const float* __restrict__ var,
    const float* __restrict__ ws,    const float* __restrict__ bs,
    const float* __restrict__ b3,    float* __restrict__ out)
{
    __shared__ float s_wr[64][16];          // pre-scaled by 0.25
    __shared__ float s_ws[36][16];
    __shared__ uint2 s_w3f[4][8][32];
    __shared__ __align__(16) char s_buf[8][6912];
    __shared__ float s_scale[16], s_shift[16], s_br[16], s_bs[36], s_b3[64];

    int tid = threadIdx.x;
    int warp = tid >> 5, lane = tid & 31;
    int qr = lane >> 2, qc = lane & 3;

    for (int i = tid; i < 1024; i += 256) {
        int r = i % 16, c = i / 16;
        s_wr[c][r] = wr[r * 64 + c] * 0.25f;
    }
    for (int i = tid; i < 576; i += 256) {
        int r = i % 16, o = i / 16;
        s_ws[o][r] = ws[o * 16 + r];
    }
    for (int i = tid; i < 1024; i += 256) ((uint2*)s_w3f)[i] = g_w3f[i];
    if (tid < 16) {
        float sc = gamma[tid] * rsqrtf(var[tid] + 1e-5f);
        s_scale[tid] = sc;
        s_shift[tid] = beta[tid] - mean[tid] * sc;
        s_br[tid] = br[tid];
    }
    if (tid < 36) s_bs[tid] = bs[tid];
    if (tid < 64) s_b3[tid] = b3[tid];
    __syncthreads();

    int idx = blockIdx.x * 256 + tid;
    int b = idx >> 16;
    int p = idx & 0xFFFF;
    int h = p >> 8;

    int p0 = (blockIdx.x * 256 + warp * 32) & 0xFFFF;
    int w0 = p0 & 255;

    const __half* Yb = g_yh + ((size_t)b << 24);
    char* bw = s_buf[warp];
    __half* wgs = (__half*)(bw + 4608);

    // ---- phase A stage: coalesced 2-row load + pool -> bw[32 px][72 halves] ----
    {
        const __half* rowA = Yb + ((size_t)(2 * h) << 15) + ((size_t)(2 * w0) << 6);
        int sub = lane >> 3, c8 = lane & 7;
#pragma unroll
        for (int i = 0; i < 16; i++) {
            int ypx = i * 4 + sub;
            const uint4* a0 = (const uint4*)(rowA + ((size_t)ypx << 6)) + c8;
            const uint4* a1 = (const uint4*)(rowA + (1 << 15) + ((size_t)ypx << 6)) + c8;
            uint4 va = *a0, vb = *a1;
            uint32_t s4[4];
            const __half2* ha = (const __half2*)&va;
            const __half2* hb = (const __half2*)&vb;
#pragma unroll
            for (int j = 0; j < 4; j++) {
                __half2 s = __hadd2(ha[j], hb[j]);
                uint32_t su = *(uint32_t*)&s;
                uint32_t pu = __shfl_xor_sync(0xffffffffu, su, 8);
                __half2 sum = __hadd2(s, *(__half2*)&pu);
                s4[j] = *(uint32_t*)&sum;
            }
            if ((sub & 1) == 0) {
                int pp = i * 2 + (sub >> 1);
                uint4 v;
                v.x = s4[0]; v.y = s4[1]; v.z = s4[2]; v.w = s4[3];
                *(uint4*)(bw + pp * 144 + c8 * 16) = v;
            }
        }
    }
    __syncwarp();

    // ---- phase A matvec: pooled (smem) -> t[16] ----
    float t[16];
#pragma unroll
    for (int r = 0; r < REDC; r++) t[r] = s_br[r];
    {
        const uint4* q = (const uint4*)(bw + lane * 144);
#pragma unroll
        for (int i = 0; i < 8; i++) {
            uint4 v = q[i];
            const __half2* hv = (const __half2*)&v;
#pragma unroll
            for (int j = 0; j < 4; j++) {
                float2 f = __half22float2(hv[j]);
                int c0 = i * 8 + j * 2;
#pragma unroll
                for (int rq = 0; rq < 4; rq++) {
                    float4 w0v = *(const float4*)&s_wr[c0][rq * 4];
                    float4 w1v = *(const float4*)&s_wr[c0 + 1][rq * 4];
                    t[rq * 4 + 0] = fmaf(f.x, w0v.x, fmaf(f.y, w1v.x, t[rq * 4 + 0]));
                    t[rq * 4 + 1] = fmaf(f.x, w0v.y, fmaf(f.y, w1v.y, t[rq * 4 + 1]));
                    t[rq * 4 + 2] = fmaf(f.x, w0v.z, fmaf(f.y, w1v.z, t[rq * 4 + 2]));
                    t[rq * 4 + 3] = fmaf(f.x, w0v.w, fmaf(f.y, w1v.w, t[rq * 4 + 3]));
                }
            }
        }
    }
#pragma unroll
    for (int r = 0; r < REDC; r++)
        t[r] = fmaxf(fmaf(t[r], s_scale[r], s_shift[r]), 0.f);

    // ---- span weights for own pixel -> smem (fp16) ----
    {
        __half* wp = wgs + lane * 36;
#pragma unroll
        for (int o = 0; o < 36; o++) {
            float a = s_bs[o];
#pragma unroll
            for (int rq = 0; rq < 4; rq++) {
                float4 wv = *(const float4*)&s_ws[o][rq * 4];
                a = fmaf(t[rq * 4 + 0], wv.x, fmaf(t[rq * 4 + 1], wv.y,
                    fmaf(t[rq * 4 + 2], wv.z, fmaf(t[rq * 4 + 3], wv.w, a))));
            }
            wp[o] = __float2half(a);
        }
    }
    __syncwarp();

    // ---- phase B: involution, lane = channel-pair, iterate 32 pixels ----
    {
        int gsel = lane >> 3;
        if (h > 0 && w0 > 0) {
            const __half2* rb[3];
            float2 carry[3];
#pragma unroll
            for (int kh = 0; kh < 3; kh++) {
                rb[kh] = (const __half2*)(Yb + (((size_t)(2 * h - 1 + kh)) << 15)
                         + (((size_t)(2 * w0 - 1)) << 6)) + lane;
                carry[kh] = __half22float2(rb[kh][0]);
            }
#pragma unroll 1
            for (int i = 0; i < 32; i++) {
                const __half* wgi = wgs + i * 36 + gsel * 9;
                float wkk[9];
#pragma unroll
                for (int k = 0; k < 9; k++) wkk[k] = __half2float(wgi[k]);
                float zx = 0.f, zy = 0.f;
#pragma unroll
                for (int kh = 0; kh < 3; kh++) {
                    float2 c1 = __half22float2(rb[kh][(2 * i + 1) * 32]);
                    float2 c2 = __half22float2(rb[kh][(2 * i + 2) * 32]);
                    zx = fmaf(wkk[kh * 3 + 0], carry[kh].x,
                         fmaf(wkk[kh * 3 + 1], c1.x,
                         fmaf(wkk[kh * 3 + 2], c2.x, zx)));
                    zy = fmaf(wkk[kh * 3 + 0], carry[kh].y,
                         fmaf(wkk[kh * 3 + 1], c1.y,
                         fmaf(wkk[kh * 3 + 2], c2.y, zy)));
                    carry[kh] = c2;
                }
                __half2 zz = __floats2half2_rn(fmaxf(zx, 0.f), fmaxf(zy, 0.f));
                *(__half2*)(bw + i * 144 + lane * 4) = zz;
            }
        } else {
#pragma unroll 1
            for (int i = 0; i < 32; i++) {
                const __half* wgi = wgs + i * 36 + gsel * 9;
                float wkk[9];
#pragma unroll
                for (int k = 0; k < 9; k++) wkk[k] = __half2float(wgi[k]);
                int wpx = w0 + i;
                float zx = 0.f, zy = 0.f;
#pragma unroll
                for (int kh = 0; kh < 3; kh++) {
                    int row = 2 * h - 1 + kh;
#pragma unroll
                    for (int kw = 0; kw < 3; kw++) {
                        int col = 2 * wpx - 1 + kw;
                        bool ok = (row >= 0) && (col >= 0);
                        const __half2* ap = (const __half2*)(Yb
                            + (((size_t)(ok ? row : 0)) << 15)
                            + (((size_t)(ok ? col : 0)) << 6)) + lane;
                        __half2 v = ok ? *ap : __float2half2_rn(0.f);
                        float2 f = __half22float2(v);
                        float wk = wkk[kh * 3 + kw];
                        zx = fmaf(wk, f.x, zx);
                        zy = fmaf(wk, f.y, zy);
                    }
                }
                __half2 zz = __floats2half2_rn(fmaxf(zx, 0.f), fmaxf(zy, 0.f));
                *(__half2*)(bw + i * 144 + lane * 4) = zz;
            }
        }
    }
    __syncwarp();

    // ---- phase C: final 1x1 via mma, output in two 32-oc halves ----
    uint32_t a[2][4][4];
    {
        uint32_t sbase = (uint32_t)__cvta_generic_to_shared(bw);
        int rsel = lane & 15, ksel = lane >> 4;
#pragma unroll
        for (int m = 0; m < 2; m++)
#pragma unroll
            for (int kk = 0; kk < 4; kk++) {
                uint32_t addr = sbase + (m * 16 + rsel) * 144 + kk * 32 + ksel * 16;
                LDMX4(a[m][kk], addr);
            }
    }
    __syncwarp();
    float* so = (float*)bw;   // [32 px][33] f32
#pragma unroll
    for (int hh = 0; hh < 2; hh++) {
#pragma unroll
        for (int nt = 0; nt < 4; nt++) {
            float d0[4] = {0.f, 0.f, 0.f, 0.f}, d1[4] = {0.f, 0.f, 0.f, 0.f};
#pragma unroll
            for (int kk = 0; kk < 4; kk++) {
                uint2 bb = s_w3f[kk][hh * 4 + nt][lane];
                mma_f16(d0, a[0][kk], bb.x, bb.y);
                mma_f16(d1, a[1][kk], bb.x, bb.y);
            }
            int oc0 = nt * 8 + qc * 2;
            so[qr * 33 + oc0]            = d0[0];
            so[qr * 33 + oc0 + 1]        = d0[1];
            so[(qr + 8) * 33 + oc0]      = d0[2];
            so[(qr + 8) * 33 + oc0 + 1]  = d0[3];
            so[(16 + qr) * 33 + oc0]     = d1[0];
            so[(16 + qr) * 33 + oc0 + 1] = d1[1];
            so[(24 + qr) * 33 + oc0]     = d1[2];
            so[(24 + qr) * 33 + oc0 + 1] = d1[3];
        }
        __syncwarp();
#pragma unroll 8
        for (int j = 0; j < 32; j++) {
            int oc = hh * 32 + j;
            float v = so[lane * 33 + j] + s_b3[oc];
            out[(((size_t)(b * 64 + oc)) << 16) + p0 + lane] = fmaxf(v, 0.f);
        }
        __syncwarp();
    }
}

// ---------------------------------------------------------------------------
extern "C" void kernel_launch(void* const* d_in, const int* in_sizes, int n_in,
                              void* d_out, int out_size)
{
    const float* x     = (const float*)d_in[0];
    const float* w1    = (const float*)d_in[1];
    const float* b1    = (const float*)d_in[2];
    const float* wr    = (const float*)d_in[3];
    const float* br    = (const float*)d_in[4];
    const float* gamma = (const float*)d_in[5];
    const float* beta  = (const float*)d_in[6];
    const float* mean  = (const float*)d_in[7];
    const float* var   = (const float*)d_in[8];
    const float* ws    = (const float*)d_in[9];
    const float* bs    = (const float*)d_in[10];
    const float* w3    = (const float*)d_in[11];
    const float* b3    = (const float*)d_in[12];
    float* out = (float*)d_out;
    (void)in_sizes; (void)n_in; (void)out_size;

    cudaFuncSetAttribute(conv_mma_kernel,
                         cudaFuncAttributeMaxDynamicSharedMemorySize, CONV_SMEM_BYTES);

    wpack_kernel<<<(NWU4 + 255) / 256, 256>>>(w1, w3);
    conv_mma_kernel<<<NCTA, 512, CONV_SMEM_BYTES>>>(x, b1);
    fuse_kernel<<<(BATCH * OH * OW) / 256, 256>>>(wr, br, gamma, beta, mean, var,
                                                  ws, bs, b3, out);
}

// round 14
// speedup vs baseline: 1.3215x; 1.3215x over previous
#include <cuda_runtime.h>
#include <cuda_fp16.h>
#include <cstdint>

#define BATCH 4
#define CH    64
#define HH    512
#define WWID  512
#define OH    256
#define OW    256
#define REDC  16
#define NWGT  36

#define NCTA     148
#define NROWU    4096           // 8 columns (4b x 2 strips) * 512 rows
#define STRIP    256
#define SLOT_PX  258
#define SLOT_B   37152          // 258 px * 144 B
#define NWU4     4608           // conv weight uint4 entries: 18*8*32

// conv smem byte offsets
#define OFF_W 0                 // uint4[4608] = 73728 B
#define OFF_X 73728             // 4 ring slots * 37152 = 148608 B
#define OFF_B 222336            // bias 64 floats
#define CONV_SMEM_BYTES 222592

// Scratch
__device__ __align__(16) __half g_yh[(size_t)BATCH * HH * WWID * CH];   // y fp16 NHWC
__device__ __align__(16) __half g_xt[(size_t)BATCH * HH * WWID * CH];   // x fp16 NHWC

// ---------------- helpers ----------------
#define CP16(dst, src, sz) \
    asm volatile("cp.async.cg.shared.global [%0], [%1], 16, %2;" \
        :: "r"(dst), "l"(src), "r"(sz) : "memory")
#define CP_COMMIT() asm volatile("cp.async.commit_group;" ::: "memory")
#define CP_WAIT0()  asm volatile("cp.async.wait_group 0;" ::: "memory")

__device__ __forceinline__ void mma_f16(float* d, const uint32_t* a,
                                        uint32_t b0, uint32_t b1) {
    asm volatile(
        "mma.sync.aligned.m16n8k16.row.col.f32.f16.f16.f32 "
        "{%0,%1,%2,%3},{%4,%5,%6,%7},{%8,%9},{%0,%1,%2,%3};"
        : "+f"(d[0]), "+f"(d[1]), "+f"(d[2]), "+f"(d[3])
        : "r"(a[0]), "r"(a[1]), "r"(a[2]), "r"(a[3]), "r"(b0), "r"(b1));
}
#define LDMX4(r, addr) \
    asm volatile("ldmatrix.sync.aligned.m8n8.x4.shared.b16 {%0,%1,%2,%3}, [%4];" \
        : "=r"((r)[0]), "=r"((r)[1]), "=r"((r)[2]), "=r"((r)[3]) : "r"(addr))

// ---------------------------------------------------------------------------
// Transpose x: NCHW fp32 -> NHWC fp16
// ---------------------------------------------------------------------------
__global__ __launch_bounds__(256) void transpose_kernel(const float* __restrict__ x)
{
    __shared__ float s[64][65];
    int tid = threadIdx.x;
    size_t P0 = (size_t)blockIdx.x * 64;
    int b = blockIdx.x >> 12;
    int ploc = (blockIdx.x & 4095) * 64;
#pragma unroll
    for (int i = 0; i < 16; i++) {
        int c = i * 4 + (tid >> 6);
        int p = tid & 63;
        s[p][c] = x[((size_t)(b * 64 + c)) * (HH * WWID) + ploc + p];
    }
    __syncthreads();
#pragma unroll
    for (int i = 0; i < 8; i++) {
        int p = i * 8 + (tid >> 5);
        int c0 = (tid & 31) * 2;
        *(__half2*)(g_xt + (P0 + p) * 64 + c0) = __floats2half2_rn(s[p][c0], s[p][c0 + 1]);
    }
}

// ---------------------------------------------------------------------------
// Persistent fp16 mma conv3x3 + bias + relu -> g_yh (fp16 NHWC).
// 148 CTAs x 512 thr; warps 0-7 compute (each m32 x n64), warps 8-15 produce.
// Prologue packs w1 into mma B-fragment layout directly (no wpack kernel).
// ---------------------------------------------------------------------------
__global__ __launch_bounds__(512, 1) void conv_mma_kernel(
    const float* __restrict__ w1, const float* __restrict__ b1)
{
    extern __shared__ char smem[];
    uint4* s_w  = (uint4*)(smem + OFF_W);
    float* s_bias = (float*)(smem + OFF_B);

    int tid = threadIdx.x;
    int warpid = tid >> 5;
    int lane = tid & 31;
    int qr = lane >> 2, qc = lane & 3;
    int cta = blockIdx.x;

    uint32_t sb  = (uint32_t)__cvta_generic_to_shared(smem);
    uint32_t sxb = sb + OFF_X;

    // prologue: pack conv weights into smem frag layout (entry = ch*256+nt*32+lane)
    for (int i = tid; i < NWU4; i += 512) {
        int l    = i & 31;
        int nt   = (i >> 5) & 7;
        int ch   = i >> 8;
        int tap = ch >> 1, sec = ch & 1;
        int oc = nt * 8 + (l >> 2);
        uint4 v;
#pragma unroll
        for (int kk = 0; kk < 2; kk++) {
            int ic0 = sec * 32 + kk * 16 + 2 * (l & 3);
            __half2 h0 = __floats2half2_rn(w1[(oc * 64 + ic0) * 9 + tap],
                                           w1[(oc * 64 + ic0 + 1) * 9 + tap]);
            __half2 h1 = __floats2half2_rn(w1[(oc * 64 + ic0 + 8) * 9 + tap],
                                           w1[(oc * 64 + ic0 + 9) * 9 + tap]);
            if (kk == 0) { v.x = *(uint32_t*)&h0; v.y = *(uint32_t*)&h1; }
            else         { v.z = *(uint32_t*)&h0; v.w = *(uint32_t*)&h1; }
        }
        s_w[i] = v;
    }
    if (tid < 64) s_bias[tid] = b1[tid];
    __syncthreads();

    int ptid = tid - 256;
    int s_idx = (int)((long long)cta * NROWU / NCTA);
    int e_idx = (int)((long long)(cta + 1) * NROWU / NCTA);

    int ms = (warpid & 7) * 32;
    uint32_t laneoff = (uint32_t)((lane & 15) * 144 + ((lane >> 4) & 1) * 16);

    int wbase = 0;
    size_t brow = 0;

#define LOAD_ROW(AR, SLOT) do { \
    int _ar = (AR), _sl = (SLOT); \
    for (int i = ptid; i < SLOT_PX * 8; i += 256) { \
        int px = i >> 3, c8 = i & 7; \
        int gw = wbase + px - 1; \
        int ok = ((unsigned)_ar < 512u) && ((unsigned)gw < 512u); \
        const __half* src = g_xt + (((brow + (ok ? _ar : 0)) << 9) + (ok ? gw : 0)) * 64 + c8 * 8; \
        CP16(sxb + _sl * SLOT_B + px * 144 + c8 * 16, src, ok ? 16 : 0); \
    } } while (0)

    int curcol = -1;
    for (int idx = s_idx; idx < e_idx; idx++) {
        int col = idx >> 9;
        int h = idx & 511;
        int b = col >> 1, strip = col & 1;
        wbase = strip * STRIP;
        brow = (size_t)b * 512;

        if (warpid >= 8) {
            if (col != curcol) {
                LOAD_ROW(h - 1, (h - 1) & 3);
                LOAD_ROW(h,     h & 3);
                LOAD_ROW(h + 1, (h + 1) & 3);
                CP_COMMIT();
            }
            CP_WAIT0();
        }
        curcol = col;
        __syncthreads();

        if (warpid < 8) {
            float acc[2][8][4];
#pragma unroll
            for (int f = 0; f < 2; f++)
#pragma unroll
                for (int nt = 0; nt < 8; nt++)
#pragma unroll
                    for (int j = 0; j < 4; j++) acc[f][nt][j] = 0.f;

#pragma unroll 1
            for (int ch = 0; ch < 18; ch++) {
                int tap = ch >> 1, sec = ch & 1;
                int kh = tap / 3, kw = tap - kh * 3;
                uint32_t abase = sxb + ((h + kh - 1) & 3) * SLOT_B
                               + (ms + kw) * 144 + sec * 64 + laneoff;
                uint32_t a0[2][4], a1[2][4];
                LDMX4(a0[0], abase);
                LDMX4(a0[1], abase + 16 * 144);
                LDMX4(a1[0], abase + 32);
                LDMX4(a1[1], abase + 32 + 16 * 144);
                const uint4* wq = s_w + ch * 256 + lane;
                uint4 bv[8];
#pragma unroll
                for (int nt = 0; nt < 8; nt++) bv[nt] = wq[nt * 32];
#pragma unroll
                for (int nt = 0; nt < 8; nt++) {
                    mma_f16(acc[0][nt], a0[0], bv[nt].x, bv[nt].y);
                    mma_f16(acc[1][nt], a0[1], bv[nt].x, bv[nt].y);
                }
#pragma unroll
                for (int nt = 0; nt < 8; nt++) {
                    mma_f16(acc[0][nt], a1[0], bv[nt].z, bv[nt].w);
                    mma_f16(acc[1][nt], a1[1], bv[nt].z, bv[nt].w);
                }
            }
            size_t rowoff = ((size_t)(b * 512 + h) << 9);
#pragma unroll
            for (int f = 0; f < 2; f++) {
                int px0 = wbase + ms + f * 16 + qr;
#pragma unroll
                for (int nt = 0; nt < 8; nt++) {
                    int oc0 = nt * 8 + qc * 2;
                    float bs0 = s_bias[oc0], bs1 = s_bias[oc0 + 1];
                    __half2 lo = __floats2half2_rn(fmaxf(acc[f][nt][0] + bs0, 0.f),
                                                   fmaxf(acc[f][nt][1] + bs1, 0.f));
                    __half2 hi = __floats2half2_rn(fmaxf(acc[f][nt][2] + bs0, 0.f),
                                                   fmaxf(acc[f][nt][3] + bs1, 0.f));
                    *(__half2*)(g_yh + ((rowoff + px0) << 6) + oc0) = lo;
                    *(__half2*)(g_yh + ((rowoff + px0 + 8) << 6) + oc0) = hi;
                }
            }
        } else {
            LOAD_ROW(h + 2, (h + 2) & 3);
            CP_COMMIT();
        }
        __syncthreads();
    }
#undef LOAD_ROW
}

// ---------------------------------------------------------------------------
// Fused tail: 256 threads (8 warps), warp = 32 consecutive output pixels.
// Prologue packs w3 fragments directly from w3 (no wpack kernel).
// ---------------------------------------------------------------------------
__global__ __launch_bounds__(256, 3) void fuse_kernel(
    const float* __restrict__ wr, const float* __restrict__ br,
    const float* __restrict__ gamma, const float* __restrict__ beta,
    const float* __restrict__ mean,  const float* __restrict__ var,
    const float* __restrict__ ws,    const float* __restrict__ bs,
    const float* __restrict__ w3,    const float* __restrict__ b3,
    float* __restrict__ out)
{
    __shared__ float s_wr[64][16];          // pre-scaled by 0.25
    __shared__ float s_ws[36][16];
    __shared__ uint2 s_w3f[4][8][32];
    __shared__ __align__(16) char s_buf[8][6912];
    __shared__ float s_scale[16], s_shift[16], s_br[16], s_bs[36], s_b3[64];

    int tid = threadIdx.x;
    int warp = tid >> 5, lane = tid & 31;
    int qr = lane >> 2, qc = lane & 3;

    for (int i = tid; i < 1024; i += 256) {
        int r = i % 16, c = i / 16;
        s_wr[c][r] = wr[r * 64 + c] * 0.25f;
    }
    for (int i = tid; i < 576; i += 256) {
        int r = i % 16, o = i / 16;
        s_ws[o][r] = ws[o * 16 + r];
    }
    for (int i = tid; i < 1024; i += 256) {
        int l    = i & 31;
        int nt   = (i >> 5) & 7;
        int kk   = i >> 8;
        int oc = nt * 8 + (l >> 2);
        int c0 = kk * 16 + 2 * (l & 3);
        __half2 h0 = __floats2half2_rn(w3[oc * 64 + c0],     w3[oc * 64 + c0 + 1]);
        __half2 h1 = __floats2half2_rn(w3[oc * 64 + c0 + 8], w3[oc * 64 + c0 + 9]);
        uint2 v;
        v.x = *(uint32_t*)&h0;
        v.y = *(uint32_t*)&h1;
        ((uint2*)s_w3f)[i] = v;
    }
    if (tid < 16) {
        float sc = gamma[tid] * rsqrtf(var[tid] + 1e-5f);
        s_scale[tid] = sc;
        s_shift[tid] = beta[tid] - mean[tid] * sc;
        s_br[tid] = br[tid];
    }
    if (tid < 36) s_bs[tid] = bs[tid];
    if (tid < 64) s_b3[tid] = b3[tid];
    __syncthreads();

    int idx = blockIdx.x * 256 + tid;
    int b = idx >> 16;
    int p = idx & 0xFFFF;
    int h = p >> 8;

    int p0 = (blockIdx.x * 256 + warp * 32) & 0xFFFF;
    int w0 = p0 & 255;

    const __half* Yb = g_yh + ((size_t)b << 24);
    char* bw = s_buf[warp];
    __half* wgs = (__half*)(bw + 4608);

    // ---- phase A stage: coalesced 2-row load + pool -> bw[32 px][72 halves] ----
    {
        const __half* rowA = Yb + ((size_t)(2 * h) << 15) + ((size_t)(2 * w0) << 6);
        int sub = lane >> 3, c8 = lane & 7;
#pragma unroll
        for (int i = 0; i < 16; i++) {
            int ypx = i * 4 + sub;
            const uint4* a0 = (const uint4*)(rowA + ((size_t)ypx << 6)) + c8;
            const uint4* a1 = (const uint4*)(rowA + (1 << 15) + ((size_t)ypx << 6)) + c8;
            uint4 va = *a0, vb = *a1;
            uint32_t s4[4];
            const __half2* ha = (const __half2*)&va;
            const __half2* hb = (const __half2*)&vb;
#pragma unroll
            for (int j = 0; j < 4; j++) {
                __half2 s = __hadd2(ha[j], hb[j]);
                uint32_t su = *(uint32_t*)&s;
                uint32_t pu = __shfl_xor_sync(0xffffffffu, su, 8);
                __half2 sum = __hadd2(s, *(__half2*)&pu);
                s4[j] = *(uint32_t*)&sum;
            }
            if ((sub & 1) == 0) {
                int pp = i * 2 + (sub >> 1);
                uint4 v;
                v.x = s4[0]; v.y = s4[1]; v.z = s4[2]; v.w = s4[3];
                *(uint4*)(bw + pp * 144 + c8 * 16) = v;
            }
        }
    }
    __syncwarp();

    // ---- phase A matvec: pooled (smem) -> t[16] ----
    float t[16];
#pragma unroll
    for (int r = 0; r < REDC; r++) t[r] = s_br[r];
    {
        const uint4* q = (const uint4*)(bw + lane * 144);
#pragma unroll
        for (int i = 0; i < 8; i++) {
            uint4 v = q[i];
            const __half2* hv = (const __half2*)&v;
#pragma unroll
            for (int j = 0; j < 4; j++) {
                float2 f = __half22float2(hv[j]);
                int c0 = i * 8 + j * 2;
#pragma unroll
                for (int rq = 0; rq < 4; rq++) {
                    float4 w0v = *(const float4*)&s_wr[c0][rq * 4];
                    float4 w1v = *(const float4*)&s_wr[c0 + 1][rq * 4];
                    t[rq * 4 + 0] = fmaf(f.x, w0v.x, fmaf(f.y, w1v.x, t[rq * 4 + 0]));
                    t[rq * 4 + 1] = fmaf(f.x, w0v.y, fmaf(f.y, w1v.y, t[rq * 4 + 1]));
                    t[rq * 4 + 2] = fmaf(f.x, w0v.z, fmaf(f.y, w1v.z, t[rq * 4 + 2]));
                    t[rq * 4 + 3] = fmaf(f.x, w0v.w, fmaf(f.y, w1v.w, t[rq * 4 + 3]));
                }
            }
        }
    }
#pragma unroll
    for (int r = 0; r < REDC; r++)
        t[r] = fmaxf(fmaf(t[r], s_scale[r], s_shift[r]), 0.f);

    // ---- span weights for own pixel -> smem (fp16) ----
    {
        __half* wp = wgs + lane * 36;
#pragma unroll
        for (int o = 0; o < 36; o++) {
            float a = s_bs[o];
#pragma unroll
            for (int rq = 0; rq < 4; rq++) {
                float4 wv = *(const float4*)&s_ws[o][rq * 4];
                a = fmaf(t[rq * 4 + 0], wv.x, fmaf(t[rq * 4 + 1], wv.y,
                    fmaf(t[rq * 4 + 2], wv.z, fmaf(t[rq * 4 + 3], wv.w, a))));
            }
            wp[o] = __float2half(a);
        }
    }
    __syncwarp();

    // ---- phase B: involution, lane = channel-pair, iterate 32 pixels ----
    {
        int gsel = lane >> 3;
        if (h > 0 && w0 > 0) {
            const __half2* rb[3];
            float2 carry[3];
#pragma unroll
            for (int kh = 0; kh < 3; kh++) {
                rb[kh] = (const __half2*)(Yb + (((size_t)(2 * h - 1 + kh)) << 15)
                         + (((size_t)(2 * w0 - 1)) << 6)) + lane;
                carry[kh] = __half22float2(rb[kh][0]);
            }
#pragma unroll 1
            for (int i = 0; i < 32; i++) {
                const __half* wgi = wgs + i * 36 + gsel * 9;
                float wkk[9];
#pragma unroll
                for (int k = 0; k < 9; k++) wkk[k] = __half2float(wgi[k]);
                float zx = 0.f, zy = 0.f;
#pragma unroll
                for (int kh = 0; kh < 3; kh++) {
                    float2 c1 = __half22float2(rb[kh][(2 * i + 1) * 32]);
                    float2 c2 = __half22float2(rb[kh][(2 * i + 2) * 32]);
                    zx = fmaf(wkk[kh * 3 + 0], carry[kh].x,
                         fmaf(wkk[kh * 3 + 1], c1.x,
                         fmaf(wkk[kh * 3 + 2], c2.x, zx)));
                    zy = fmaf(wkk[kh * 3 + 0], carry[kh].y,
                         fmaf(wkk[kh * 3 + 1], c1.y,
                         fmaf(wkk[kh * 3 + 2], c2.y, zy)));
                    carry[kh] = c2;
                }
                __half2 zz = __floats2half2_rn(fmaxf(zx, 0.f), fmaxf(zy, 0.f));
                *(__half2*)(bw + i * 144 + lane * 4) = zz;
            }
        } else {
#pragma unroll 1
            for (int i = 0; i < 32; i++) {
                const __half* wgi = wgs + i * 36 + gsel * 9;
                float wkk[9];
#pragma unroll
                for (int k = 0; k < 9; k++) wkk[k] = __half2float(wgi[k]);
                int wpx = w0 + i;
                float zx = 0.f, zy = 0.f;
#pragma unroll
                for (int kh = 0; kh < 3; kh++) {
                    int row = 2 * h - 1 + kh;
#pragma unroll
                    for (int kw = 0; kw < 3; kw++) {
                        int col = 2 * wpx - 1 + kw;
                        bool ok = (row >= 0) && (col >= 0);
                        const __half2* ap = (const __half2*)(Yb
                            + (((size_t)(ok ? row : 0)) << 15)
                            + (((size_t)(ok ? col : 0)) << 6)) + lane;
                        __half2 v = ok ? *ap : __float2half2_rn(0.f);
                        float2 f = __half22float2(v);
                        float wk = wkk[kh * 3 + kw];
                        zx = fmaf(wk, f.x, zx);
                        zy = fmaf(wk, f.y, zy);
                    }
                }
                __half2 zz = __floats2half2_rn(fmaxf(zx, 0.f), fmaxf(zy, 0.f));
                *(__half2*)(bw + i * 144 + lane * 4) = zz;
            }
        }
    }
    __syncwarp();

    // ---- phase C: final 1x1 via mma, output in two 32-oc halves ----
    uint32_t a[2][4][4];
    {
        uint32_t sbase = (uint32_t)__cvta_generic_to_shared(bw);
        int rsel = lane & 15, ksel = lane >> 4;
#pragma unroll
        for (int m = 0; m < 2; m++)
#pragma unroll
            for (int kk = 0; kk < 4; kk++) {
                uint32_t addr = sbase + (m * 16 + rsel) * 144 + kk * 32 + ksel * 16;
                LDMX4(a[m][kk], addr);
            }
    }
    __syncwarp();
    float* so = (float*)bw;   // [32 px][33] f32
#pragma unroll
    for (int hh = 0; hh < 2; hh++) {
#pragma unroll
        for (int nt = 0; nt < 4; nt++) {
            float d0[4] = {0.f, 0.f, 0.f, 0.f}, d1[4] = {0.f, 0.f, 0.f, 0.f};
#pragma unroll
            for (int kk = 0; kk < 4; kk++) {
                uint2 bb = s_w3f[kk][hh * 4 + nt][lane];
                mma_f16(d0, a[0][kk], bb.x, bb.y);
                mma_f16(d1, a[1][kk], bb.x, bb.y);
            }
            int oc0 = nt * 8 + qc * 2;
            so[qr * 33 + oc0]            = d0[0];
            so[qr * 33 + oc0 + 1]        = d0[1];
            so[(qr + 8) * 33 + oc0]      = d0[2];
            so[(qr + 8) * 33 + oc0 + 1]  = d0[3];
            so[(16 + qr) * 33 + oc0]     = d1[0];
            so[(16 + qr) * 33 + oc0 + 1] = d1[1];
            so[(24 + qr) * 33 + oc0]     = d1[2];
            so[(24 + qr) * 33 + oc0 + 1] = d1[3];
        }
        __syncwarp();
#pragma unroll 8
        for (int j = 0; j < 32; j++) {
            int oc = hh * 32 + j;
            float v = so[lane * 33 + j] + s_b3[oc];
            out[(((size_t)(b * 64 + oc)) << 16) + p0 + lane] = fmaxf(v, 0.f);
        }
        __syncwarp();
    }
}

// ---------------------------------------------------------------------------
extern "C" void kernel_launch(void* const* d_in, const int* in_sizes, int n_in,
                              void* d_out, int out_size)
{
    const float* x     = (const float*)d_in[0];
    const float* w1    = (const float*)d_in[1];
    const float* b1    = (const float*)d_in[2];
    const float* wr    = (const float*)d_in[3];
    const float* br    = (const float*)d_in[4];
    const float* gamma = (const float*)d_in[5];
    const float* beta  = (const float*)d_in[6];
    const float* mean  = (const float*)d_in[7];
    const float* var   = (const float*)d_in[8];
    const float* ws    = (const float*)d_in[9];
    const float* bs    = (const float*)d_in[10];
    const float* w3    = (const float*)d_in[11];
    const float* b3    = (const float*)d_in[12];
    float* out = (float*)d_out;
    (void)in_sizes; (void)n_in; (void)out_size;

    cudaFuncSetAttribute(conv_mma_kernel,
                         cudaFuncAttributeMaxDynamicSharedMemorySize, CONV_SMEM_BYTES);

    transpose_kernel<<<16384, 256>>>(x);
    conv_mma_kernel<<<NCTA, 512, CONV_SMEM_BYTES>>>(w1, b1);
    fuse_kernel<<<(BATCH * OH * OW) / 256, 256>>>(wr, br, gamma, beta, mean, var,
                                                  ws, bs, w3, b3, out);
}

// round 16
// speedup vs baseline: 1.3892x; 1.0512x over previous
#include <cuda_runtime.h>
#include <cuda_fp16.h>
#include <cstdint>

#define BATCH 4
#define CH    64
#define HH    512
#define WWID  512
#define OH    256
#define OW    256
#define REDC  16
#define NWGT  36

#define NCTA     148
#define NROWU    4096           // 8 columns (4b x 2 strips) * 512 rows
#define STRIP    256
#define SLOT_PX  258
#define SLOT_B   37152          // 258 px * 144 B
#define NWU4     4608           // conv weight uint4 entries: 18*8*32

// conv smem byte offsets
#define OFF_W 0                 // uint4[4608] = 73728 B
#define OFF_X 73728             // 4 ring slots * 37152 = 148608 B
#define OFF_B 222336            // bias 64 floats
#define CONV_SMEM_BYTES 222592

// Scratch
__device__ __align__(16) __half g_yh[(size_t)BATCH * HH * WWID * CH];   // y fp16 NHWC
__device__ __align__(16) __half g_xt[(size_t)BATCH * HH * WWID * CH];   // x fp16 NHWC
__device__ __align__(16) uint4  g_wh[NWU4];                             // conv weight frags
__device__ __align__(16) uint2  g_w3f[1024];                            // w3 frags

// ---------------- helpers ----------------
#define CP16(dst, src, sz) \
    asm volatile("cp.async.cg.shared.global [%0], [%1], 16, %2;" \
        :: "r"(dst), "l"(src), "r"(sz) : "memory")
#define CP_COMMIT() asm volatile("cp.async.commit_group;" ::: "memory")
#define CP_WAIT0()  asm volatile("cp.async.wait_group 0;" ::: "memory")

__device__ __forceinline__ void mma_f16(float* d, const uint32_t* a,
                                        uint32_t b0, uint32_t b1) {
    asm volatile(
        "mma.sync.aligned.m16n8k16.row.col.f32.f16.f16.f32 "
        "{%0,%1,%2,%3},{%4,%5,%6,%7},{%8,%9},{%0,%1,%2,%3};"
        : "+f"(d[0]), "+f"(d[1]), "+f"(d[2]), "+f"(d[3])
        : "r"(a[0]), "r"(a[1]), "r"(a[2]), "r"(a[3]), "r"(b0), "r"(b1));
}
#define LDMX4(r, addr) \
    asm volatile("ldmatrix.sync.aligned.m8n8.x4.shared.b16 {%0,%1,%2,%3}, [%4];" \
        : "=r"((r)[0]), "=r"((r)[1]), "=r"((r)[2]), "=r"((r)[3]) : "r"(addr))

// ---------------------------------------------------------------------------
// Transpose x: NCHW fp32 -> NHWC fp16. float4 gmem loads, uint4 gmem stores,
// scalar (legal, conflict-free) smem reads.
// ---------------------------------------------------------------------------
__global__ __launch_bounds__(256) void transpose_kernel(const float* __restrict__ x)
{
    __shared__ float s[64][65];
    int tid = threadIdx.x;
    size_t P0 = (size_t)blockIdx.x * 64;
    int b = blockIdx.x >> 12;
    int ploc = (blockIdx.x & 4095) * 64;

    // phase 1: 1024 float4 loads (4 per thread), coalesced per channel row
#pragma unroll
    for (int k = 0; k < 4; k++) {
        int i = tid + k * 256;
        int c  = i >> 4;          // 0..63
        int p4 = i & 15;          // 0..15
        float4 v = *(const float4*)(x + ((size_t)(b * 64 + c) << 18) + ploc + p4 * 4);
        s[p4 * 4 + 0][c] = v.x;
        s[p4 * 4 + 1][c] = v.y;
        s[p4 * 4 + 2][c] = v.z;
        s[p4 * 4 + 3][c] = v.w;
    }
    __syncthreads();

    // phase 2: each thread emits 2 x 16B gmem stores (scalar smem reads)
#pragma unroll
    for (int k = 0; k < 2; k++) {
        int i = tid + k * 256;
        int p  = i >> 3;          // 0..63
        int c8 = i & 7;           // 0..7
        const float* sp = &s[p][c8 * 8];
        __half2 h0 = __floats2half2_rn(sp[0], sp[1]);
        __half2 h1 = __floats2half2_rn(sp[2], sp[3]);
        __half2 h2 = __floats2half2_rn(sp[4], sp[5]);
        __half2 h3 = __floats2half2_rn(sp[6], sp[7]);
        uint4 o;
        o.x = *(uint32_t*)&h0; o.y = *(uint32_t*)&h1;
        o.z = *(uint32_t*)&h2; o.w = *(uint32_t*)&h3;
        *(uint4*)(g_xt + (P0 + p) * 64 + c8 * 8) = o;
    }
}

// ---------------------------------------------------------------------------
// Pack conv weights: uint4 entry idx = ch*256 + nt*32 + lane holds both kk
// halves. Also w3 frags.
// ---------------------------------------------------------------------------
__global__ __launch_bounds__(256) void wpack_kernel(const float* __restrict__ w1,
                                                    const float* __restrict__ w3)
{
    int idx = blockIdx.x * 256 + threadIdx.x;
    if (idx < NWU4) {
        int lane = idx & 31;
        int nt   = (idx >> 5) & 7;
        int ch   = idx >> 8;
        int tap = ch >> 1, sec = ch & 1;
        int oc = nt * 8 + (lane >> 2);
        uint4 v;
#pragma unroll
        for (int kk = 0; kk < 2; kk++) {
            int ic0 = sec * 32 + kk * 16 + 2 * (lane & 3);
            __half2 h0 = __floats2half2_rn(w1[(oc * 64 + ic0) * 9 + tap],
                                           w1[(oc * 64 + ic0 + 1) * 9 + tap]);
            __half2 h1 = __floats2half2_rn(w1[(oc * 64 + ic0 + 8) * 9 + tap],
                                           w1[(oc * 64 + ic0 + 9) * 9 + tap]);
            if (kk == 0) { v.x = *(uint32_t*)&h0; v.y = *(uint32_t*)&h1; }
            else         { v.z = *(uint32_t*)&h0; v.w = *(uint32_t*)&h1; }
        }
        g_wh[idx] = v;
    }
    if (idx < 1024) {
        int lane = idx & 31;
        int nt   = (idx >> 5) & 7;
        int kk   = idx >> 8;
        int oc = nt * 8 + (lane >> 2);
        int c0 = kk * 16 + 2 * (lane & 3);
        __half2 h0 = __floats2half2_rn(w3[oc * 64 + c0],     w3[oc * 64 + c0 + 1]);
        __half2 h1 = __floats2half2_rn(w3[oc * 64 + c0 + 8], w3[oc * 64 + c0 + 9]);
        uint2 v;
        v.x = *(uint32_t*)&h0;
        v.y = *(uint32_t*)&h1;
        g_w3f[idx] = v;
    }
}

// ---------------------------------------------------------------------------
// Persistent fp16 mma conv3x3 + bias + relu -> g_yh (fp16 NHWC).
// 148 CTAs x 512 thr; warps 0-7 compute (each m32 x n64), warps 8-15 produce.
// ---------------------------------------------------------------------------
__global__ __launch_bounds__(512, 1) void conv_mma_kernel(const float* __restrict__ b1)
{
    extern __shared__ char smem[];
    uint4* s_w  = (uint4*)(smem + OFF_W);
    float* s_bias = (float*)(smem + OFF_B);

    int tid = threadIdx.x;
    int warpid = tid >> 5;
    int lane = tid & 31;
    int qr = lane >> 2, qc = lane & 3;
    int cta = blockIdx.x;

    uint32_t sb  = (uint32_t)__cvta_generic_to_shared(smem);
    uint32_t sxb = sb + OFF_X;

    for (int i = tid; i < NWU4; i += 512)
        CP16(sb + OFF_W + i * 16, (const char*)g_wh + i * 16, 16);
    if (tid < 64) s_bias[tid] = b1[tid];
    CP_COMMIT();
    CP_WAIT0();
    __syncthreads();

    int ptid = tid - 256;
    int s_idx = (int)((long long)cta * NROWU / NCTA);
    int e_idx = (int)((long long)(cta + 1) * NROWU / NCTA);

    int ms = (warpid & 7) * 32;
    uint32_t laneoff = (uint32_t)((lane & 15) * 144 + ((lane >> 4) & 1) * 16);

    int wbase = 0;
    size_t brow = 0;

#define LOAD_ROW(AR, SLOT) do { \
    int _ar = (AR), _sl = (SLOT); \
    for (int i = ptid; i < SLOT_PX * 8; i += 256) { \
        int px = i >> 3, c8 = i & 7; \
        int gw = wbase + px - 1; \
        int ok = ((unsigned)_ar < 512u) && ((unsigned)gw < 512u); \
        const __half* src = g_xt + (((brow + (ok ? _ar : 0)) << 9) + (ok ? gw : 0)) * 64 + c8 * 8; \
        CP16(sxb + _sl * SLOT_B + px * 144 + c8 * 16, src, ok ? 16 : 0); \
    } } while (0)

    int curcol = -1;
    for (int idx = s_idx; idx < e_idx; idx++) {
        int col = idx >> 9;
        int h = idx & 511;
        int b = col >> 1, strip = col & 1;
        wbase = strip * STRIP;
        brow = (size_t)b * 512;

        if (warpid >= 8) {
            if (col != curcol) {
                LOAD_ROW(h - 1, (h - 1) & 3);
                LOAD_ROW(h,     h & 3);
                LOAD_ROW(h + 1, (h + 1) & 3);
                CP_COMMIT();
            }
            CP_WAIT0();
        }
        curcol = col;
        __syncthreads();

        if (warpid < 8) {
            float acc[2][8][4];
#pragma unroll
            for (int f = 0; f < 2; f++)
#pragma unroll
                for (int nt = 0; nt < 8; nt++)
#pragma unroll
                    for (int j = 0; j < 4; j++) acc[f][nt][j] = 0.f;

#pragma unroll 1
            for (int ch = 0; ch < 18; ch++) {
                int tap = ch >> 1, sec = ch & 1;
                int kh = tap / 3, kw = tap - kh * 3;
                uint32_t abase = sxb + ((h + kh - 1) & 3) * SLOT_B
                               + (ms + kw) * 144 + sec * 64 + laneoff;
                uint32_t a0[2][4], a1[2][4];
                LDMX4(a0[0], abase);
                LDMX4(a0[1], abase + 16 * 144);
                LDMX4(a1[0], abase + 32);
                LDMX4(a1[1], abase + 32 + 16 * 144);
                const uint4* wq = s_w + ch * 256 + lane;
                uint4 bv[8];
#pragma unroll
                for (int nt = 0; nt < 8; nt++) bv[nt] = wq[nt * 32];
#pragma unroll
                for (int nt = 0; nt < 8; nt++) {
                    mma_f16(acc[0][nt], a0[0], bv[nt].x, bv[nt].y);
                    mma_f16(acc[1][nt], a0[1], bv[nt].x, bv[nt].y);
                }
#pragma unroll
                for (int nt = 0; nt < 8; nt++) {
                    mma_f16(acc[0][nt], a1[0], bv[nt].z, bv[nt].w);
                    mma_f16(acc[1][nt], a1[1], bv[nt].z, bv[nt].w);
                }
            }
            size_t rowoff = ((size_t)(b * 512 + h) << 9);
#pragma unroll
            for (int f = 0; f < 2; f++) {
                int px0 = wbase + ms + f * 16 + qr;
#pragma unroll
                for (int nt = 0; nt < 8; nt++) {
                    int oc0 = nt * 8 + qc * 2;
                    float bs0 = s_bias[oc0], bs1 = s_bias[oc0 + 1];
                    __half2 lo = __floats2half2_rn(fmaxf(acc[f][nt][0] + bs0, 0.f),
                                                   fmaxf(acc[f][nt][1] + bs1, 0.f));
                    __half2 hi = __floats2half2_rn(fmaxf(acc[f][nt][2] + bs0, 0.f),
                                                   fmaxf(acc[f][nt][3] + bs1, 0.f));
                    *(__half2*)(g_yh + ((rowoff + px0) << 6) + oc0) = lo;
                    *(__half2*)(g_yh + ((rowoff + px0 + 8) << 6) + oc0) = hi;
                }
            }
        } else {
            LOAD_ROW(h + 2, (h + 2) & 3);
            CP_COMMIT();
        }
        __syncthreads();
    }
#undef LOAD_ROW
}

// ---------------------------------------------------------------------------
// Fused tail: 256 threads (8 warps), warp = 32 consecutive output pixels.
// ---------------------------------------------------------------------------
__global__ __launch_bounds__(256, 3) void fuse_kernel(
    const float* __restrict__ wr, const float* __restrict__ br,
    const float* __restrict__ gamma, const float* __restrict__ beta,
    const float* __restrict__ mean,  const float* __restrict__ var,
    const float* __restrict__ ws,    const float* __restrict__ bs,
    const float* __restrict__ b3,    float* __restrict__ out)
{
    __shared__ float s_wr[64][16];          // pre-scaled by 0.25
    __shared__ float s_ws[36][16];
    __shared__ uint2 s_w3f[4][8][32];
    __shared__ __align__(16) char s_buf[8][6912];
    __shared__ float s_scale[16], s_shift[16], s_br[16], s_bs[36], s_b3[64];

    int tid = threadIdx.x;
    int warp = tid >> 5, lane = tid & 31;
    int qr = lane >> 2, qc = lane & 3;

    for (int i = tid; i < 1024; i += 256) {
        int r = i % 16, c = i / 16;
        s_wr[c][r] = wr[r * 64 + c] * 0.25f;
    }
    for (int i = tid; i < 576; i += 256) {
        int r = i % 16, o = i / 16;
        s_ws[o][r] = ws[o * 16 + r];
    }
    for (int i = tid; i < 1024; i += 256) ((uint2*)s_w3f)[i] = g_w3f[i];
    if (tid < 16) {
        float sc = gamma[tid] * rsqrtf(var[tid] + 1e-5f);
        s_scale[tid] = sc;
        s_shift[tid] = beta[tid] - mean[tid] * sc;
        s_br[tid] = br[tid];
    }
    if (tid < 36) s_bs[tid] = bs[tid];
    if (tid < 64) s_b3[tid] = b3[tid];
    __syncthreads();

    int idx = blockIdx.x * 256 + tid;
    int b = idx >> 16;
    int p = idx & 0xFFFF;
    int h = p >> 8;

    int p0 = (blockIdx.x * 256 + warp * 32) & 0xFFFF;
    int w0 = p0 & 255;

    const __half* Yb = g_yh + ((size_t)b << 24);
    char* bw = s_buf[warp];
    __half* wgs = (__half*)(bw + 4608);

    // ---- phase A stage: coalesced 2-row load + pool -> bw[32 px][72 halves] ----
    {
        const __half* rowA = Yb + ((size_t)(2 * h) << 15) + ((size_t)(2 * w0) << 6);
        int sub = lane >> 3, c8 = lane & 7;
#pragma unroll
        for (int i = 0; i < 16; i++) {
            int ypx = i * 4 + sub;
            const uint4* a0 = (const uint4*)(rowA + ((size_t)ypx << 6)) + c8;
            const uint4* a1 = (const uint4*)(rowA + (1 << 15) + ((size_t)ypx << 6)) + c8;
            uint4 va = *a0, vb = *a1;
            uint32_t s4[4];
            const __half2* ha = (const __half2*)&va;
            const __half2* hb = (const __half2*)&vb;
#pragma unroll
            for (int j = 0; j < 4; j++) {
                __half2 s = __hadd2(ha[j], hb[j]);
                uint32_t su = *(uint32_t*)&s;
                uint32_t pu = __shfl_xor_sync(0xffffffffu, su, 8);
                __half2 sum = __hadd2(s, *(__half2*)&pu);
                s4[j] = *(uint32_t*)&sum;
            }
            if ((sub & 1) == 0) {
                int pp = i * 2 + (sub >> 1);
                uint4 v;
                v.x = s4[0]; v.y = s4[1]; v.z = s4[2]; v.w = s4[3];
                *(uint4*)(bw + pp * 144 + c8 * 16) = v;
            }
        }
    }
    __syncwarp();

    // ---- phase A matvec: pooled (smem) -> t[16] ----
    float t[16];
#pragma unroll
    for (int r = 0; r < REDC; r++) t[r] = s_br[r];
    {
        const uint4* q = (const uint4*)(bw + lane * 144);
#pragma unroll
        for (int i = 0; i < 8; i++) {
            uint4 v = q[i];
            const __half2* hv = (const __half2*)&v;
#pragma unroll
            for (int j = 0; j < 4; j++) {
                float2 f = __half22float2(hv[j]);
                int c0 = i * 8 + j * 2;
#pragma unroll
                for (int rq = 0; rq < 4; rq++) {
                    float4 w0v = *(const float4*)&s_wr[c0][rq * 4];
                    float4 w1v = *(const float4*)&s_wr[c0 + 1][rq * 4];
                    t[rq * 4 + 0] = fmaf(f.x, w0v.x, fmaf(f.y, w1v.x, t[rq * 4 + 0]));
                    t[rq * 4 + 1] = fmaf(f.x, w0v.y, fmaf(f.y, w1v.y, t[rq * 4 + 1]));
                    t[rq * 4 + 2] = fmaf(f.x, w0v.z, fmaf(f.y, w1v.z, t[rq * 4 + 2]));
                    t[rq * 4 + 3] = fmaf(f.x, w0v.w, fmaf(f.y, w1v.w, t[rq * 4 + 3]));
                }
            }
        }
    }
#pragma unroll
    for (int r = 0; r < REDC; r++)
        t[r] = fmaxf(fmaf(t[r], s_scale[r], s_shift[r]), 0.f);

    // ---- span weights for own pixel -> smem (fp16) ----
    {
        __half* wp = wgs + lane * 36;
#pragma unroll
        for (int o = 0; o < 36; o++) {
            float a = s_bs[o];
#pragma unroll
            for (int rq = 0; rq < 4; rq++) {
                float4 wv = *(const float4*)&s_ws[o][rq * 4];
                a = fmaf(t[rq * 4 + 0], wv.x, fmaf(t[rq * 4 + 1], wv.y,
                    fmaf(t[rq * 4 + 2], wv.z, fmaf(t[rq * 4 + 3], wv.w, a))));
            }
            wp[o] = __float2half(a);
        }
    }
    __syncwarp();

    // ---- phase B: involution, lane = channel-pair, iterate 32 pixels ----
    {
        int gsel = lane >> 3;
        if (h > 0 && w0 > 0) {
            const __half2* rb[3];
            float2 carry[3];
#pragma unroll
            for (int kh = 0; kh < 3; kh++) {
                rb[kh] = (const __half2*)(Yb + (((size_t)(2 * h - 1 + kh)) << 15)
                         + (((size_t)(2 * w0 - 1)) << 6)) + lane;
                carry[kh] = __half22float2(rb[kh][0]);
            }
#pragma unroll 1
            for (int i = 0; i < 32; i++) {
                const __half* wgi = wgs + i * 36 + gsel * 9;
                float wkk[9];
#pragma unroll
                for (int k = 0; k < 9; k++) wkk[k] = __half2float(wgi[k]);
                float zx = 0.f, zy = 0.f;
#pragma unroll
                for (int kh = 0; kh < 3; kh++) {
                    float2 c1 = __half22float2(rb[kh][(2 * i + 1) * 32]);
                    float2 c2 = __half22float2(rb[kh][(2 * i + 2) * 32]);
                    zx = fmaf(wkk[kh * 3 + 0], carry[kh].x,
                         fmaf(wkk[kh * 3 + 1], c1.x,
                         fmaf(wkk[kh * 3 + 2], c2.x, zx)));
                    zy = fmaf(wkk[kh * 3 + 0], carry[kh].y,
                         fmaf(wkk[kh * 3 + 1], c1.y,
                         fmaf(wkk[kh * 3 + 2], c2.y, zy)));
                    carry[kh] = c2;
                }
                __half2 zz = __floats2half2_rn(fmaxf(zx, 0.f), fmaxf(zy, 0.f));
                *(__half2*)(bw + i * 144 + lane * 4) = zz;
            }
        } else {
#pragma unroll 1
            for (int i = 0; i < 32; i++) {
                const __half* wgi = wgs + i * 36 + gsel * 9;
                float wkk[9];
#pragma unroll
                for (int k = 0; k < 9; k++) wkk[k] = __half2float(wgi[k]);
                int wpx = w0 + i;
                float zx = 0.f, zy = 0.f;
#pragma unroll
                for (int kh = 0; kh < 3; kh++) {
                    int row = 2 * h - 1 + kh;
#pragma unroll
                    for (int kw = 0; kw < 3; kw++) {
                        int col = 2 * wpx - 1 + kw;
                        bool ok = (row >= 0) && (col >= 0);
                        const __half2* ap = (const __half2*)(Yb
                            + (((size_t)(ok ? row : 0)) << 15)
                            + (((size_t)(ok ? col : 0)) << 6)) + lane;
                        __half2 v = ok ? *ap : __float2half2_rn(0.f);
                        float2 f = __half22float2(v);
                        float wk = wkk[kh * 3 + kw];
                        zx = fmaf(wk, f.x, zx);
                        zy = fmaf(wk, f.y, zy);
                    }
                }
                __half2 zz = __floats2half2_rn(fmaxf(zx, 0.f), fmaxf(zy, 0.f));
                *(__half2*)(bw + i * 144 + lane * 4) = zz;
            }
        }
    }
    __syncwarp();

    // ---- phase C: final 1x1 via mma, output in two 32-oc halves ----
    uint32_t a[2][4][4];
    {
        uint32_t sbase = (uint32_t)__cvta_generic_to_shared(bw);
        int rsel = lane & 15, ksel = lane >> 4;
#pragma unroll
        for (int m = 0; m < 2; m++)
#pragma unroll
            for (int kk = 0; kk < 4; kk++) {
                uint32_t addr = sbase + (m * 16 + rsel) * 144 + kk * 32 + ksel * 16;
                LDMX4(a[m][kk], addr);
            }
    }
    __syncwarp();
    float* so = (float*)bw;   // [32 px][33] f32
#pragma unroll
    for (int hh = 0; hh < 2; hh++) {
#pragma unroll
        for (int nt = 0; nt < 4; nt++) {
            float d0[4] = {0.f, 0.f, 0.f, 0.f}, d1[4] = {0.f, 0.f, 0.f, 0.f};
#pragma unroll
            for (int kk = 0; kk < 4; kk++) {
                uint2 bb = s_w3f[kk][hh * 4 + nt][lane];
                mma_f16(d0, a[0][kk], bb.x, bb.y);
                mma_f16(d1, a[1][kk], bb.x, bb.y);
            }
            int oc0 = nt * 8 + qc * 2;
            so[qr * 33 + oc0]            = d0[0];
            so[qr * 33 + oc0 + 1]        = d0[1];
            so[(qr + 8) * 33 + oc0]      = d0[2];
            so[(qr + 8) * 33 + oc0 + 1]  = d0[3];
            so[(16 + qr) * 33 + oc0]     = d1[0];
            so[(16 + qr) * 33 + oc0 + 1] = d1[1];
            so[(24 + qr) * 33 + oc0]     = d1[2];
            so[(24 + qr) * 33 + oc0 + 1] = d1[3];
        }
        __syncwarp();
#pragma unroll 8
        for (int j = 0; j < 32; j++) {
            int oc = hh * 32 + j;
            float v = so[lane * 33 + j] + s_b3[oc];
            out[(((size_t)(b * 64 + oc)) << 16) + p0 + lane] = fmaxf(v, 0.f);
        }
        __syncwarp();
    }
}

// ---------------------------------------------------------------------------
extern "C" void kernel_launch(void* const* d_in, const int* in_sizes, int n_in,
                              void* d_out, int out_size)
{
    const float* x     = (const float*)d_in[0];
    const float* w1    = (const float*)d_in[1];
    const float* b1    = (const float*)d_in[2];
    const float* wr    = (const float*)d_in[3];
    const float* br    = (const float*)d_in[4];
    const float* gamma = (const float*)d_in[5];
    const float* beta  = (const float*)d_in[6];
    const float* mean  = (const float*)d_in[7];
    const float* var   = (const float*)d_in[8];
    const float* ws    = (const float*)d_in[9];
    const float* bs    = (const float*)d_in[10];
    const float* w3    = (const float*)d_in[11];
    const float* b3    = (const float*)d_in[12];
    float* out = (float*)d_out;
    (void)in_sizes; (void)n_in; (void)out_size;

    cudaFuncSetAttribute(conv_mma_kernel,
                         cudaFuncAttributeMaxDynamicSharedMemorySize, CONV_SMEM_BYTES);

    transpose_kernel<<<16384, 256>>>(x);
    wpack_kernel<<<(NWU4 + 255) / 256, 256>>>(w1, w3);
    conv_mma_kernel<<<NCTA, 512, CONV_SMEM_BYTES>>>(b1);
    fuse_kernel<<<(BATCH * OH * OW) / 256, 256>>>(wr, br, gamma, beta, mean, var,
                                                  ws, bs, b3, out);
}